// round 12
// baseline (speedup 1.0000x reference)
#include <cuda_runtime.h>
#include <cuda_fp16.h>
#include <stdint.h>

// ---------------------------------------------------------------------------
// Problem constants
// ---------------------------------------------------------------------------
#define B_   16
#define C_   256
#define HW_  1024
#define NTOK 16384                 // tokens
#define K_   8192                  // codebook entries
#define NOUT (B_ * C_ * HW_)       // 4194304

#define MTILE  128                 // tokens per CTA
#define NTILE  128                 // codes per chunk
#define NCHUNK (K_ / NTILE)        // 64
#define NCTA   (NTOK / MTILE)      // 128

// SMEM map (bytes)
#define SA      0                  // A: 128 rows x 512B (fp16)
#define SAE     65536              // A-ext: 128 rows x 32B (const -1,-1,0..)
#define SB      69632              // B: 2 stages x 65536 (128 rows x 512B)
#define SBE     200704             // B-ext: 2 stages x 4096 (e2 hi/lo rows)
#define SMRG    208896             // 128 tokens x 4 groups x 16B = 8192
#define SBARS   217088
#define SMEM_SZ 217216

#define BAR_AF    (SBARS + 0)
#define BAR_BF(s) (SBARS + 8 + 8*(s))    // B stage full
#define BAR_BE(s) (SBARS + 24 + 8*(s))   // B stage empty (512 consumer arrivals)

// ---------------------------------------------------------------------------
// Device-global scratch. Per token/code: 256 ch x 2B fp16 = 512B = 32 uint4.
// ---------------------------------------------------------------------------
__device__ __align__(128) uint4 g_ximg4[NTOK * 32];   // 8 MB fp16 slab images
__device__ __align__(128) uint4 g_cbimg4[K_ * 32];    // 4 MB fp16 chunk images
__device__ __align__(128) uint4 g_beimg4[K_ * 2];     // 256KB: ext k-step rows (e2hi,e2lo,0..)
__device__ __align__(128) float g_e2h[K_];            // 0.5*||e_k||^2 exact (fixup)
__device__ int4  g_cand[NTOK];                        // {i1, i2, bits(gap), 0}
__device__ int   g_idx[NTOK];
__device__ float g_loss;

// ---------------------------------------------------------------------------
// PTX helpers (non-'a' features only: safe for compute_103)
// ---------------------------------------------------------------------------
__device__ __forceinline__ uint32_t smem_to_u32(const void* p) {
    uint32_t a;
    asm("{ .reg .u64 t; cvta.to.shared.u64 t, %1; cvt.u32.u64 %0, t; }" : "=r"(a) : "l"(p));
    return a;
}

#define MBARRIER_INIT(addr, cnt) \
    asm volatile("mbarrier.init.shared.b64 [%0], %1;" :: "r"((uint32_t)(addr)), "r"((uint32_t)(cnt)) : "memory")

#define MBARRIER_EXPECT_TX(addr, bytes) \
    asm volatile("mbarrier.arrive.expect_tx.shared.b64 _, [%0], %1;" :: "r"((uint32_t)(addr)), "r"((uint32_t)(bytes)) : "memory")

#define MBARRIER_ARRIVE(addr) \
    asm volatile("mbarrier.arrive.shared.b64 _, [%0];" :: "r"((uint32_t)(addr)) : "memory")

#define MBARRIER_WAIT_PARITY(addr, par) do {                                     \
    uint32_t _m = (uint32_t)(addr); uint32_t _p = (uint32_t)(par); uint32_t _d;  \
    asm volatile("{\n\t.reg .pred p;\n\t"                                        \
        "mbarrier.try_wait.parity.acquire.cta.shared::cta.b64 p, [%1], %2;\n\t"  \
        "selp.b32 %0, 1, 0, p;\n\t}"                                             \
        : "=r"(_d) : "r"(_m), "r"(_p) : "memory");                               \
    if (!_d) {                                                                   \
        asm volatile("{\n\t.reg .pred P1;\n\t"                                   \
            "WL_%=:\n\t"                                                         \
            "mbarrier.try_wait.parity.acquire.cta.shared::cta.b64 P1, [%0], %1, 0x989680;\n\t" \
            "@P1 bra.uni WD_%=;\n\t"                                             \
            "bra.uni WL_%=;\n\t"                                                 \
            "WD_%=:\n\t}" :: "r"(_m), "r"(_p) : "memory");                       \
    }                                                                            \
} while (0)

__device__ __forceinline__ void bulk_g2s(uint32_t dst, const void* src, uint32_t bytes, uint32_t mbar) {
    asm volatile("cp.async.bulk.shared::cta.global.mbarrier::complete_tx::bytes [%0], [%1], %2, [%3];"
        :: "r"(dst), "l"(src), "r"(bytes), "r"(mbar) : "memory");
}

__device__ __forceinline__ void ldsm4(uint32_t addr, uint32_t r[4]) {
    asm volatile("ldmatrix.sync.aligned.m8n8.x4.shared.b16 {%0,%1,%2,%3}, [%4];"
        : "=r"(r[0]), "=r"(r[1]), "=r"(r[2]), "=r"(r[3]) : "r"(addr));
}

__device__ __forceinline__ void mma_f16(float d[4], const uint32_t a[4], uint32_t b0, uint32_t b1) {
    asm volatile("mma.sync.aligned.m16n8k16.row.col.f32.f16.f16.f32 "
        "{%0,%1,%2,%3}, {%4,%5,%6,%7}, {%8,%9}, {%0,%1,%2,%3};"
        : "+f"(d[0]), "+f"(d[1]), "+f"(d[2]), "+f"(d[3])
        : "r"(a[0]), "r"(a[1]), "r"(a[2]), "r"(a[3]), "r"(b0), "r"(b1));
}

// 8 HMMA: m32 x n32 x k16
__device__ __forceinline__ void mma_block(float acc[2][4][4],
        const uint32_t A0[4], const uint32_t A1[4],
        const uint32_t Q0[4], const uint32_t Q1[4]) {
    mma_f16(acc[0][0], A0, Q0[0], Q0[2]);
    mma_f16(acc[0][1], A0, Q0[1], Q0[3]);
    mma_f16(acc[0][2], A0, Q1[0], Q1[2]);
    mma_f16(acc[0][3], A0, Q1[1], Q1[3]);
    mma_f16(acc[1][0], A1, Q0[0], Q0[2]);
    mma_f16(acc[1][1], A1, Q0[1], Q0[3]);
    mma_f16(acc[1][2], A1, Q1[0], Q1[2]);
    mma_f16(acc[1][3], A1, Q1[1], Q1[3]);
}

__device__ __forceinline__ unsigned long long packkey(float s, int idx) {
    unsigned int b = __float_as_uint(s);
    unsigned int su = (b & 0x80000000u) ? ~b : (b | 0x80000000u);
    return ((unsigned long long)su << 32) | (unsigned int)idx;
}
__device__ __forceinline__ float unpackscore(unsigned long long k) {
    unsigned int su = (unsigned int)(k >> 32);
    unsigned int b = (su & 0x80000000u) ? (su ^ 0x80000000u) : ~su;
    return __uint_as_float(b);
}
__device__ __forceinline__ unsigned long long u64min(unsigned long long a, unsigned long long b) { return a < b ? a : b; }
__device__ __forceinline__ unsigned long long u64max(unsigned long long a, unsigned long long b) { return a > b ? a : b; }

// pack 8 floats -> 8 fp16 in one uint4
__device__ __forceinline__ uint4 pack8h(const float* f) {
    uint32_t w[4];
#pragma unroll
    for (int p = 0; p < 4; p++) {
        __half2 h = __floats2half2_rn(f[2 * p], f[2 * p + 1]);
        w[p] = *(uint32_t*)&h;
    }
    return make_uint4(w[0], w[1], w[2], w[3]);
}

// ---------------------------------------------------------------------------
// Prep 1: codebook -> swizzled fp16 images + ext rows (e2 hi/lo) + exact e2.
// Row r at r*512B within its 128-row stage; 16B chunk l stored at l^(r&7).
// ---------------------------------------------------------------------------
__global__ void prep_cb_kernel(const float* __restrict__ cb) {
    if (blockIdx.x == 0 && threadIdx.x == 0) g_loss = 0.0f;
    int n = (blockIdx.x * blockDim.x + threadIdx.x) >> 5;
    int l = threadIdx.x & 31;
    if (n >= K_) return;
    const float* row = cb + (size_t)n * C_;
    float f[8];
    float ss = 0.0f;
#pragma unroll
    for (int j = 0; j < 8; j++) { f[j] = row[8 * l + j]; ss += f[j] * f[j]; }
    g_cbimg4[n * 32 + (l ^ (n & 7))] = pack8h(f);
#pragma unroll
    for (int o = 16; o; o >>= 1) ss += __shfl_xor_sync(0xffffffffu, ss, o);
    if (l == 0) {
        float e2 = 0.5f * ss;
        g_e2h[n] = e2;
        __half h1 = __float2half(e2);
        __half h2 = __float2half(e2 - __half2float(h1));
        uint32_t p01 = (uint32_t)*(unsigned short*)&h1 | ((uint32_t)*(unsigned short*)&h2 << 16);
        g_beimg4[n * 2]     = make_uint4(p01, 0u, 0u, 0u);   // ch0=e2hi, ch1=e2lo
        g_beimg4[n * 2 + 1] = make_uint4(0u, 0u, 0u, 0u);    // ch8..15 = 0
    }
}

// ---------------------------------------------------------------------------
// Prep 2: x [B,C,H,W] -> token-major swizzled fp16 slab images.
// ---------------------------------------------------------------------------
__global__ void prep_x_kernel(const float* __restrict__ x) {
    __shared__ float tile[32][33];
    int b = blockIdx.z, hw0 = blockIdx.x * 32, c0 = blockIdx.y * 32;
    int tx = threadIdx.x, ty = threadIdx.y;
#pragma unroll
    for (int i = 0; i < 4; i++) {
        int c = c0 + ty + 8 * i;
        tile[ty + 8 * i][tx] = x[((size_t)b * C_ + c) * HW_ + hw0 + tx];
    }
    __syncthreads();
    int t = ty * 32 + tx;
    if (t < 128) {
        int hwl = t >> 2;
        int cg  = t & 3;
        float f[8];
#pragma unroll
        for (int j = 0; j < 8; j++) f[j] = tile[cg * 8 + j][hwl];
        int token = b * HW_ + hw0 + hwl;
        int slab = token >> 7, m = token & 127;
        int cchunk = (c0 >> 3) + cg;
        g_ximg4[slab * 4096 + m * 32 + (cchunk ^ (m & 7))] = pack8h(f);
    }
}

// Padding no-op so the fixed ncu capture window (-s 5 -c 1) lands on vq_main.
__global__ void noop_kernel() {}

// ---------------------------------------------------------------------------
// Main: single-pass fp16 mma.sync GEMM (17 k-steps: 256 ch + e2 fold) +
// per-token top-2 argmax of acc = x.e - 0.5*||e||^2.
// 128 CTAs x 544 threads: warps 0-15 compute (4 m-bands x 4 n-bands of m32n32),
// warp 16 produces. Chunk = 128 codes, B double-buffered.
// ---------------------------------------------------------------------------
__global__ __launch_bounds__(544, 1) void vq_main_kernel() {
    extern __shared__ __align__(128) char smem[];
    uint32_t sb = smem_to_u32(smem);
    int tid = threadIdx.x;

    if (tid == 0) {
        MBARRIER_INIT(sb + BAR_AF, 1);
        MBARRIER_INIT(sb + BAR_BF(0), 1);
        MBARRIER_INIT(sb + BAR_BF(1), 1);
        MBARRIER_INIT(sb + BAR_BE(0), 512);
        MBARRIER_INIT(sb + BAR_BE(1), 512);
        asm volatile("fence.proxy.async.shared::cta;" ::: "memory");
    }
    // A-ext constant tile: each row = [-1, -1, 0 x14] fp16
    if (tid < 128) {
        uint4* ae = (uint4*)(smem + SAE);
        ae[tid * 2]     = make_uint4(0xBC00BC00u, 0u, 0u, 0u);
        ae[tid * 2 + 1] = make_uint4(0u, 0u, 0u, 0u);
    }
    __syncthreads();

    if (tid < 512) {
        const int l   = tid & 31;
        const int wid = tid >> 5;
        const int m0  = (wid & 3) * 32;     // token band
        const int nb  = (wid >> 2) * 32;    // code band within 128-code chunk
        const uint32_t kadd = (uint32_t)(l >> 4);
        const uint32_t swz  = (uint32_t)(l & 7);

        const uint32_t ra = (uint32_t)(m0 + (l & 15));
        uint32_t pa0 = sb + SA + ra * 512, pa1 = pa0 + 8192;
        const uint32_t rboff = (uint32_t)(nb + (l & 15)) * 512;

        // A-ext fragments: constant across chunks, hoisted
        uint32_t AE0[4], AE1[4];
        {
            uint32_t ua = sb + SAE + (uint32_t)(m0 + (l & 15)) * 32 + kadd * 16;
            ldsm4(ua, AE0);
            ldsm4(ua + 512, AE1);
        }

        float a1[4], a2[4];                 // running top-2 MAX of acc
        int   bi1[4], bi2[4];
#pragma unroll
        for (int t = 0; t < 4; t++) { a1[t] = -3.0e38f; a2[t] = -3.0e38f; bi1[t] = 0; bi2[t] = 0; }

        MBARRIER_WAIT_PARITY(sb + BAR_AF, 0);

        for (int i = 0; i < NCHUNK; i++) {
            int s = i & 1, ph = (i >> 1) & 1;
            float acc[2][4][4];
#pragma unroll
            for (int a = 0; a < 2; a++)
#pragma unroll
                for (int b = 0; b < 4; b++)
#pragma unroll
                    for (int c = 0; c < 4; c++) acc[a][b][c] = 0.0f;

            MBARRIER_WAIT_PARITY(sb + BAR_BF(s), ph);
            uint32_t pb0 = sb + SB + s * 65536 + rboff;   // rows nb+0..15
            uint32_t pb1 = pb0 + 8192;                    // rows nb+16..31

            // double-buffered fragment pipeline over 16 k-steps
            uint32_t A0[2][4], A1[2][4], Q0[2][4], Q1[2][4];
            {
                uint32_t u = ((kadd ^ swz) << 4);
                ldsm4(pa0 + u, A0[0]);
                ldsm4(pa1 + u, A1[0]);
                ldsm4(pb0 + u, Q0[0]);
                ldsm4(pb1 + u, Q1[0]);
            }
#pragma unroll
            for (int ks = 0; ks < 16; ks++) {
                int cur = ks & 1, nxt = cur ^ 1;
                if (ks < 15) {
                    uint32_t u = (((2u * (ks + 1) + kadd) ^ swz) << 4);
                    ldsm4(pa0 + u, A0[nxt]);
                    ldsm4(pa1 + u, A1[nxt]);
                    ldsm4(pb0 + u, Q0[nxt]);
                    ldsm4(pb1 + u, Q1[nxt]);
                }
                mma_block(acc, A0[cur], A1[cur], Q0[cur], Q1[cur]);
            }
            // 17th k-step: fold -0.5||e||^2 via A-ext x B-ext
            {
                uint32_t ue = sb + SBE + s * 4096 + (uint32_t)(nb + (l & 15)) * 32 + kadd * 16;
                uint32_t QE0[4], QE1[4];
                ldsm4(ue, QE0);
                ldsm4(ue + 512, QE1);
                mma_block(acc, AE0, AE1, QE0, QE1);
            }

            // epilogue: max-tree per 8-acc group, rare top-2 insert
            int clbase = nb + 2 * (l & 3);
#pragma unroll
            for (int t = 0; t < 4; t++) {          // t = mi*2 + rowhalf
                float v0 = acc[t >> 1][0][(t & 1) * 2 + 0];
                float v1 = acc[t >> 1][0][(t & 1) * 2 + 1];
                float v2 = acc[t >> 1][1][(t & 1) * 2 + 0];
                float v3 = acc[t >> 1][1][(t & 1) * 2 + 1];
                float v4 = acc[t >> 1][2][(t & 1) * 2 + 0];
                float v5 = acc[t >> 1][2][(t & 1) * 2 + 1];
                float v6 = acc[t >> 1][3][(t & 1) * 2 + 0];
                float v7 = acc[t >> 1][3][(t & 1) * 2 + 1];
                float mm = fmaxf(fmaxf(fmaxf(v0, v1), fmaxf(v2, v3)),
                                 fmaxf(fmaxf(v4, v5), fmaxf(v6, v7)));
                if (mm > a2[t]) {
#pragma unroll
                    for (int j = 0; j < 8; j++) {   // ascending code order: ties -> lowest idx
                        int code = i * NTILE + clbase + (j >> 1) * 8 + (j & 1);
                        float v = acc[t >> 1][j >> 1][(t & 1) * 2 + (j & 1)];
                        if (v > a1[t])      { a2[t] = a1[t]; bi2[t] = bi1[t]; a1[t] = v; bi1[t] = code; }
                        else if (v > a2[t]) { a2[t] = v; bi2[t] = code; }
                    }
                }
            }
            MBARRIER_ARRIVE(sb + BAR_BE(s));
        }

        // convert to score domain and merge (lanes sharing l>>2 own same rows)
        unsigned long long k1[4], k2[4];
#pragma unroll
        for (int t = 0; t < 4; t++) { k1[t] = packkey(-a1[t], bi1[t]); k2[t] = packkey(-a2[t], bi2[t]); }
#pragma unroll
        for (int off = 1; off <= 2; off <<= 1) {
#pragma unroll
            for (int t = 0; t < 4; t++) {
                unsigned long long o1 = __shfl_xor_sync(0xffffffffu, k1[t], off);
                unsigned long long o2 = __shfl_xor_sync(0xffffffffu, k2[t], off);
                unsigned long long n1 = u64min(k1[t], o1);
                unsigned long long n2 = u64min(u64max(k1[t], o1), u64min(k2[t], o2));
                k1[t] = n1; k2[t] = n2;
            }
        }
        uint4* mrg = (uint4*)(smem + SMRG);
        if ((l & 3) == 0) {
#pragma unroll
            for (int t = 0; t < 4; t++) {
                int tok = m0 + (t >> 1) * 16 + (l >> 2) + 8 * (t & 1);
                mrg[tok * 4 + (wid >> 2)] = make_uint4(
                    (uint32_t)(k1[t] >> 32), (uint32_t)k1[t],
                    (uint32_t)(k2[t] >> 32), (uint32_t)k2[t]);
            }
        }
        asm volatile("bar.sync 1, 512;" ::: "memory");
        if (tid < 128) {
            unsigned long long m1 = 0xFFFFFFFFFFFFFFFFULL, m2 = 0xFFFFFFFFFFFFFFFFULL;
#pragma unroll
            for (int g = 0; g < 4; g++) {
                uint4 e = mrg[tid * 4 + g];
                unsigned long long c1 = ((unsigned long long)e.x << 32) | e.y;
                unsigned long long c2 = ((unsigned long long)e.z << 32) | e.w;
                unsigned long long n1 = u64min(m1, c1);
                unsigned long long n2 = u64min(u64max(m1, c1), u64min(m2, c2));
                m1 = n1; m2 = n2;
            }
            float gap = unpackscore(m2) - unpackscore(m1);
            g_cand[blockIdx.x * MTILE + tid] = make_int4(
                (int)(uint32_t)m1, (int)(uint32_t)m2, __float_as_int(gap), 0);
        }
    } else if (tid == 512) {
        // producer
        const char* asrc = (const char*)g_ximg4 + (size_t)blockIdx.x * 65536;
        const char* bsrc = (const char*)g_cbimg4;
        const char* besrc = (const char*)g_beimg4;
        MBARRIER_EXPECT_TX(sb + BAR_AF, 65536);
        bulk_g2s(sb + SA, asrc, 32768, sb + BAR_AF);
        bulk_g2s(sb + SA + 32768, asrc + 32768, 32768, sb + BAR_AF);
        for (int i = 0; i < NCHUNK; i++) {
            int s = i & 1;
            MBARRIER_WAIT_PARITY(sb + BAR_BE(s), ((i >> 1) & 1) ^ 1);
            MBARRIER_EXPECT_TX(sb + BAR_BF(s), 65536 + 4096);
            bulk_g2s(sb + SB + s * 65536, bsrc + (size_t)i * 65536, 65536, sb + BAR_BF(s));
            bulk_g2s(sb + SBE + s * 4096, besrc + (size_t)i * 4096, 4096, sb + BAR_BF(s));
        }
    }
}

// ---------------------------------------------------------------------------
// Fixup: exact fp32 recheck of top-2 where the approx gap is small. Warp/token.
// ---------------------------------------------------------------------------
__global__ void fixup_kernel(const float* __restrict__ x, const float* __restrict__ cb) {
    int w = (blockIdx.x * blockDim.x + threadIdx.x) >> 5;
    int l = threadIdx.x & 31;
    if (w >= NTOK) return;
    int4 cd = g_cand[w];
    float gap = __int_as_float(cd.z);
    if (gap > 0.15f) { if (l == 0) g_idx[w] = cd.x; return; }
    int b = w >> 10, hw = w & (HW_ - 1);
    const float* xp = x + (size_t)b * C_ * HW_ + hw;
    const float* c1 = cb + (size_t)cd.x * C_;
    const float* c2 = cb + (size_t)cd.y * C_;
    float d1 = 0.0f, d2 = 0.0f;
    for (int c = l; c < C_; c += 32) {
        float xv = xp[(size_t)c * HW_];
        d1 += xv * c1[c];
        d2 += xv * c2[c];
    }
#pragma unroll
    for (int o = 16; o; o >>= 1) {
        d1 += __shfl_xor_sync(0xffffffffu, d1, o);
        d2 += __shfl_xor_sync(0xffffffffu, d2, o);
    }
    if (l == 0) {
        float e1 = g_e2h[cd.x] - d1, e2v = g_e2h[cd.y] - d2;
        int pick = cd.x;
        if (e2v < e1 || (e2v == e1 && cd.y < cd.x)) pick = cd.y;
        g_idx[w] = pick;
    }
}

// ---------------------------------------------------------------------------
// Gather quantized output [B,C,H,W] + MSE partial sums.
// ---------------------------------------------------------------------------
__global__ __launch_bounds__(256)
void gather_loss_kernel(const float* __restrict__ x,
                        const float* __restrict__ cb,
                        float* __restrict__ out) {
    __shared__ float warp_sums[8];
    int o = blockIdx.x * blockDim.x + threadIdx.x;
    int hw = o & (HW_ - 1);
    int bc = o >> 10;
    int c  = bc & (C_ - 1);
    int b  = bc >> 8;
    int n  = b * HW_ + hw;

    int idx  = g_idx[n];
    float q  = __ldg(&cb[(size_t)idx * C_ + c]);
    float xv = x[o];
    out[o] = q;
    float d = q - xv;
    float s = d * d;
#pragma unroll
    for (int off = 16; off; off >>= 1) s += __shfl_xor_sync(0xffffffffu, s, off);
    int lane = threadIdx.x & 31, wid = threadIdx.x >> 5;
    if (lane == 0) warp_sums[wid] = s;
    __syncthreads();
    if (wid == 0) {
        float v = (lane < 8) ? warp_sums[lane] : 0.0f;
#pragma unroll
        for (int off = 4; off; off >>= 1) v += __shfl_xor_sync(0xffffffffu, v, off);
        if (lane == 0) atomicAdd(&g_loss, v);
    }
}

__global__ void finalize_kernel(float* __restrict__ out, int out_size) {
    float m = g_loss * (1.0f / (float)NOUT);
    if (out_size >= NOUT + 1) out[NOUT] = m;
    if (out_size >= NOUT + 2) out[NOUT + 1] = m;
}

// ---------------------------------------------------------------------------
extern "C" void kernel_launch(void* const* d_in, const int* in_sizes, int n_in,
                              void* d_out, int out_size) {
    const float* x  = (const float*)d_in[0];   // [16,256,32,32]
    const float* cb = (const float*)d_in[1];   // [8192,256]
    float* out = (float*)d_out;

    cudaFuncSetAttribute(vq_main_kernel, cudaFuncAttributeMaxDynamicSharedMemorySize, SMEM_SZ);

    prep_cb_kernel<<<K_ / 8, 256>>>(cb);
    dim3 gx(32, 8, 16), bx(32, 8);
    prep_x_kernel<<<gx, bx>>>(x);
    noop_kernel<<<1, 1>>>();                               // pad: vq_main -> launch #4
    vq_main_kernel<<<NCTA, 544, SMEM_SZ>>>();
    fixup_kernel<<<NTOK / 8, 256>>>(x, cb);
    gather_loss_kernel<<<NOUT / 256, 256>>>(x, cb, out);
    finalize_kernel<<<1, 1>>>(out, out_size);
}

// round 16
// speedup vs baseline: 1.0351x; 1.0351x over previous
#include <cuda_runtime.h>
#include <cuda_fp16.h>
#include <stdint.h>

// ---------------------------------------------------------------------------
// Problem constants
// ---------------------------------------------------------------------------
#define B_   16
#define C_   256
#define HW_  1024
#define NTOK 16384                 // tokens
#define K_   8192                  // codebook entries
#define NOUT (B_ * C_ * HW_)       // 4194304

#define MTILE  128                 // tokens per CTA
#define NTILE  128                 // codes per chunk
#define NCHUNK (K_ / NTILE)        // 64
#define NCTA   (NTOK / MTILE)      // 128

// SMEM map (bytes)
#define SA      0                  // A: 128 rows x 512B (fp16)
#define SB      65536              // B: 2 stages x 65536 (128 rows x 512B)
#define SE2     196608             // 2 stages x 512B (0.5*||e||^2 chunk)
#define SMRG    197632             // 128 tokens x 4 groups x 16B = 8192
#define SBARS   205824
#define SMEM_SZ 205952

#define BAR_AF    (SBARS + 0)
#define BAR_BF(s) (SBARS + 8 + 8*(s))    // B stage full
#define BAR_BE(s) (SBARS + 24 + 8*(s))   // B stage empty (512 consumer arrivals)

// ---------------------------------------------------------------------------
// Device-global scratch. Per token/code: 256 ch x 2B fp16 = 512B = 32 uint4.
// ---------------------------------------------------------------------------
__device__ __align__(128) uint4 g_ximg4[NTOK * 32];   // 8 MB fp16 slab images
__device__ __align__(128) uint4 g_cbimg4[K_ * 32];    // 4 MB fp16 chunk images
__device__ __align__(128) float g_e2h[K_];            // 0.5*||e_k||^2 exact
__device__ int4  g_cand[NTOK];                        // {i1, i2, bits(gap), 0}
__device__ int   g_idx[NTOK];
__device__ float g_loss;

// ---------------------------------------------------------------------------
// PTX helpers (non-'a' features only: safe for compute_103)
// ---------------------------------------------------------------------------
__device__ __forceinline__ uint32_t smem_to_u32(const void* p) {
    uint32_t a;
    asm("{ .reg .u64 t; cvta.to.shared.u64 t, %1; cvt.u32.u64 %0, t; }" : "=r"(a) : "l"(p));
    return a;
}

#define MBARRIER_INIT(addr, cnt) \
    asm volatile("mbarrier.init.shared.b64 [%0], %1;" :: "r"((uint32_t)(addr)), "r"((uint32_t)(cnt)) : "memory")

#define MBARRIER_EXPECT_TX(addr, bytes) \
    asm volatile("mbarrier.arrive.expect_tx.shared.b64 _, [%0], %1;" :: "r"((uint32_t)(addr)), "r"((uint32_t)(bytes)) : "memory")

#define MBARRIER_ARRIVE(addr) \
    asm volatile("mbarrier.arrive.shared.b64 _, [%0];" :: "r"((uint32_t)(addr)) : "memory")

#define MBARRIER_WAIT_PARITY(addr, par) do {                                     \
    uint32_t _m = (uint32_t)(addr); uint32_t _p = (uint32_t)(par); uint32_t _d;  \
    asm volatile("{\n\t.reg .pred p;\n\t"                                        \
        "mbarrier.try_wait.parity.acquire.cta.shared::cta.b64 p, [%1], %2;\n\t"  \
        "selp.b32 %0, 1, 0, p;\n\t}"                                             \
        : "=r"(_d) : "r"(_m), "r"(_p) : "memory");                               \
    if (!_d) {                                                                   \
        asm volatile("{\n\t.reg .pred P1;\n\t"                                   \
            "WL_%=:\n\t"                                                         \
            "mbarrier.try_wait.parity.acquire.cta.shared::cta.b64 P1, [%0], %1, 0x989680;\n\t" \
            "@P1 bra.uni WD_%=;\n\t"                                             \
            "bra.uni WL_%=;\n\t"                                                 \
            "WD_%=:\n\t}" :: "r"(_m), "r"(_p) : "memory");                       \
    }                                                                            \
} while (0)

__device__ __forceinline__ void bulk_g2s(uint32_t dst, const void* src, uint32_t bytes, uint32_t mbar) {
    asm volatile("cp.async.bulk.shared::cta.global.mbarrier::complete_tx::bytes [%0], [%1], %2, [%3];"
        :: "r"(dst), "l"(src), "r"(bytes), "r"(mbar) : "memory");
}

__device__ __forceinline__ void ldsm4(uint32_t addr, uint32_t r[4]) {
    asm volatile("ldmatrix.sync.aligned.m8n8.x4.shared.b16 {%0,%1,%2,%3}, [%4];"
        : "=r"(r[0]), "=r"(r[1]), "=r"(r[2]), "=r"(r[3]) : "r"(addr));
}

__device__ __forceinline__ void mma_f16(float d[4], const uint32_t a[4], uint32_t b0, uint32_t b1) {
    asm volatile("mma.sync.aligned.m16n8k16.row.col.f32.f16.f16.f32 "
        "{%0,%1,%2,%3}, {%4,%5,%6,%7}, {%8,%9}, {%0,%1,%2,%3};"
        : "+f"(d[0]), "+f"(d[1]), "+f"(d[2]), "+f"(d[3])
        : "r"(a[0]), "r"(a[1]), "r"(a[2]), "r"(a[3]), "r"(b0), "r"(b1));
}

// d = a*b + c (c = separate zero quad; avoids per-chunk acc zeroing)
__device__ __forceinline__ void mma_f16_zc(float d[4], const uint32_t a[4], uint32_t b0, uint32_t b1,
                                           const float z[4]) {
    asm volatile("mma.sync.aligned.m16n8k16.row.col.f32.f16.f16.f32 "
        "{%0,%1,%2,%3}, {%4,%5,%6,%7}, {%8,%9}, {%10,%11,%12,%13};"
        : "=f"(d[0]), "=f"(d[1]), "=f"(d[2]), "=f"(d[3])
        : "r"(a[0]), "r"(a[1]), "r"(a[2]), "r"(a[3]), "r"(b0), "r"(b1),
          "f"(z[0]), "f"(z[1]), "f"(z[2]), "f"(z[3]));
}

// 8 HMMA: m32 x n32 x k16 (accumulate)
__device__ __forceinline__ void mma_block(float acc[2][4][4],
        const uint32_t A0[4], const uint32_t A1[4],
        const uint32_t Q0[4], const uint32_t Q1[4]) {
    mma_f16(acc[0][0], A0, Q0[0], Q0[2]);
    mma_f16(acc[0][1], A0, Q0[1], Q0[3]);
    mma_f16(acc[0][2], A0, Q1[0], Q1[2]);
    mma_f16(acc[0][3], A0, Q1[1], Q1[3]);
    mma_f16(acc[1][0], A1, Q0[0], Q0[2]);
    mma_f16(acc[1][1], A1, Q0[1], Q0[3]);
    mma_f16(acc[1][2], A1, Q1[0], Q1[2]);
    mma_f16(acc[1][3], A1, Q1[1], Q1[3]);
}

// 8 HMMA with zero C (first k-step of each chunk)
__device__ __forceinline__ void mma_block_zc(float acc[2][4][4],
        const uint32_t A0[4], const uint32_t A1[4],
        const uint32_t Q0[4], const uint32_t Q1[4], const float z[4]) {
    mma_f16_zc(acc[0][0], A0, Q0[0], Q0[2], z);
    mma_f16_zc(acc[0][1], A0, Q0[1], Q0[3], z);
    mma_f16_zc(acc[0][2], A0, Q1[0], Q1[2], z);
    mma_f16_zc(acc[0][3], A0, Q1[1], Q1[3], z);
    mma_f16_zc(acc[1][0], A1, Q0[0], Q0[2], z);
    mma_f16_zc(acc[1][1], A1, Q0[1], Q0[3], z);
    mma_f16_zc(acc[1][2], A1, Q1[0], Q1[2], z);
    mma_f16_zc(acc[1][3], A1, Q1[1], Q1[3], z);
}

__device__ __forceinline__ unsigned long long packkey(float s, int idx) {
    unsigned int b = __float_as_uint(s);
    unsigned int su = (b & 0x80000000u) ? ~b : (b | 0x80000000u);
    return ((unsigned long long)su << 32) | (unsigned int)idx;
}
__device__ __forceinline__ float unpackscore(unsigned long long k) {
    unsigned int su = (unsigned int)(k >> 32);
    unsigned int b = (su & 0x80000000u) ? (su ^ 0x80000000u) : ~su;
    return __uint_as_float(b);
}
__device__ __forceinline__ unsigned long long u64min(unsigned long long a, unsigned long long b) { return a < b ? a : b; }
__device__ __forceinline__ unsigned long long u64max(unsigned long long a, unsigned long long b) { return a > b ? a : b; }

// pack 8 floats -> 8 fp16 in one uint4
__device__ __forceinline__ uint4 pack8h(const float* f) {
    uint32_t w[4];
#pragma unroll
    for (int p = 0; p < 4; p++) {
        __half2 h = __floats2half2_rn(f[2 * p], f[2 * p + 1]);
        w[p] = *(uint32_t*)&h;
    }
    return make_uint4(w[0], w[1], w[2], w[3]);
}

// ---------------------------------------------------------------------------
// Prep 1: codebook -> swizzled fp16 images + 0.5*||e||^2 (+ zero loss).
// Row r at r*512B within its 128-row stage; 16B chunk l stored at l^(r&7).
// ---------------------------------------------------------------------------
__global__ void prep_cb_kernel(const float* __restrict__ cb) {
    if (blockIdx.x == 0 && threadIdx.x == 0) g_loss = 0.0f;
    int n = (blockIdx.x * blockDim.x + threadIdx.x) >> 5;
    int l = threadIdx.x & 31;
    if (n >= K_) return;
    const float* row = cb + (size_t)n * C_;
    float f[8];
    float ss = 0.0f;
#pragma unroll
    for (int j = 0; j < 8; j++) { f[j] = row[8 * l + j]; ss += f[j] * f[j]; }
    g_cbimg4[n * 32 + (l ^ (n & 7))] = pack8h(f);
#pragma unroll
    for (int o = 16; o; o >>= 1) ss += __shfl_xor_sync(0xffffffffu, ss, o);
    if (l == 0) g_e2h[n] = 0.5f * ss;
}

// ---------------------------------------------------------------------------
// Prep 2: x [B,C,H,W] -> token-major swizzled fp16 slab images.
// ---------------------------------------------------------------------------
__global__ void prep_x_kernel(const float* __restrict__ x) {
    __shared__ float tile[32][33];
    int b = blockIdx.z, hw0 = blockIdx.x * 32, c0 = blockIdx.y * 32;
    int tx = threadIdx.x, ty = threadIdx.y;
#pragma unroll
    for (int i = 0; i < 4; i++) {
        int c = c0 + ty + 8 * i;
        tile[ty + 8 * i][tx] = x[((size_t)b * C_ + c) * HW_ + hw0 + tx];
    }
    __syncthreads();
    int t = ty * 32 + tx;
    if (t < 128) {
        int hwl = t >> 2;
        int cg  = t & 3;
        float f[8];
#pragma unroll
        for (int j = 0; j < 8; j++) f[j] = tile[cg * 8 + j][hwl];
        int token = b * HW_ + hw0 + hwl;
        int slab = token >> 7, m = token & 127;
        int cchunk = (c0 >> 3) + cg;
        g_ximg4[slab * 4096 + m * 32 + (cchunk ^ (m & 7))] = pack8h(f);
    }
}

// Padding no-op so the fixed ncu capture window (-s 5 -c 1) lands on vq_main.
__global__ void noop_kernel() {}

// ---------------------------------------------------------------------------
// Main: single-pass fp16 mma.sync GEMM + per-token top-2 argmin.
// 128 CTAs x 544 threads: warps 0-15 compute (4 m-bands x 4 n-bands of m32n32),
// warp 16 produces. Chunk = 128 codes, B double-buffered (2 x 64KB).
// Fragment lookahead = 2 k-steps (3-deep ring) to cover LDSM latency;
// first k-step uses zero-C MMA (no per-chunk acc zeroing).
// score = 0.5*||e||^2 - x.e  (same argmin as squared euclidean distance)
// ---------------------------------------------------------------------------
__global__ __launch_bounds__(544, 1) void vq_main_kernel() {
    extern __shared__ __align__(128) char smem[];
    uint32_t sb = smem_to_u32(smem);
    int tid = threadIdx.x;

    if (tid == 0) {
        MBARRIER_INIT(sb + BAR_AF, 1);
        MBARRIER_INIT(sb + BAR_BF(0), 1);
        MBARRIER_INIT(sb + BAR_BF(1), 1);
        MBARRIER_INIT(sb + BAR_BE(0), 512);
        MBARRIER_INIT(sb + BAR_BE(1), 512);
        asm volatile("fence.proxy.async.shared::cta;" ::: "memory");
    }
    __syncthreads();

    if (tid < 512) {
        const int l   = tid & 31;
        const int wid = tid >> 5;
        const int m0  = (wid & 3) * 32;     // token band
        const int nb  = (wid >> 2) * 32;    // code band within 128-code chunk
        const uint32_t kadd = (uint32_t)(l >> 4);
        const uint32_t swz  = (uint32_t)(l & 7);

        const uint32_t ra = (uint32_t)(m0 + (l & 15));
        uint32_t pa0 = sb + SA + ra * 512, pa1 = pa0 + 8192;
        const uint32_t rboff = (uint32_t)(nb + (l & 15)) * 512;

        float zq[4] = {0.0f, 0.0f, 0.0f, 0.0f};
        float bs1[4], bs2[4];
        int   bi1[4], bi2[4];
#pragma unroll
        for (int t = 0; t < 4; t++) { bs1[t] = 3.0e38f; bs2[t] = 3.0e38f; bi1[t] = 0; bi2[t] = 0; }

        MBARRIER_WAIT_PARITY(sb + BAR_AF, 0);

        for (int i = 0; i < NCHUNK; i++) {
            int s = i & 1, ph = (i >> 1) & 1;
            float acc[2][4][4];

            MBARRIER_WAIT_PARITY(sb + BAR_BF(s), ph);
            uint32_t pb0 = sb + SB + s * 65536 + rboff;   // rows nb+0..15
            uint32_t pb1 = pb0 + 8192;                    // rows nb+16..31

            // 3-deep fragment ring: lookahead 2 k-steps
            uint32_t A0[3][4], A1[3][4], Q0[3][4], Q1[3][4];
#pragma unroll
            for (int p = 0; p < 2; p++) {
                uint32_t u = (((2u * p + kadd) ^ swz) << 4);
                ldsm4(pa0 + u, A0[p]);
                ldsm4(pa1 + u, A1[p]);
                ldsm4(pb0 + u, Q0[p]);
                ldsm4(pb1 + u, Q1[p]);
            }
#pragma unroll
            for (int ks = 0; ks < 16; ks++) {
                int cur = ks % 3;
                if (ks < 14) {
                    int nx = (ks + 2) % 3;
                    uint32_t u = (((2u * (ks + 2) + kadd) ^ swz) << 4);
                    ldsm4(pa0 + u, A0[nx]);
                    ldsm4(pa1 + u, A1[nx]);
                    ldsm4(pb0 + u, Q0[nx]);
                    ldsm4(pb1 + u, Q1[nx]);
                }
                if (ks == 0) mma_block_zc(acc, A0[cur], A1[cur], Q0[cur], Q1[cur], zq);
                else         mma_block(acc, A0[cur], A1[cur], Q0[cur], Q1[cur]);
            }

            // epilogue: min-tree per 8-score group, rare top-2 insert
            const float* e2s = (const float*)(smem + SE2 + s * 512);
            int clbase = nb + 2 * (l & 3);
#pragma unroll
            for (int t = 0; t < 4; t++) {          // t = mi*2 + rowhalf
                float sc[8];
#pragma unroll
                for (int j = 0; j < 8; j++) {      // j = nj*2 + col
                    int cl = clbase + (j >> 1) * 8 + (j & 1);
                    sc[j] = e2s[cl] - acc[t >> 1][j >> 1][(t & 1) * 2 + (j & 1)];
                }
                float m01 = fminf(sc[0], sc[1]), m23 = fminf(sc[2], sc[3]);
                float m45 = fminf(sc[4], sc[5]), m67 = fminf(sc[6], sc[7]);
                float mm = fminf(fminf(m01, m23), fminf(m45, m67));
                if (mm < bs2[t]) {
#pragma unroll
                    for (int j = 0; j < 8; j++) {   // ascending code order: ties -> lowest idx
                        int code = i * NTILE + clbase + (j >> 1) * 8 + (j & 1);
                        float v = sc[j];
                        if (v < bs1[t])      { bs2[t] = bs1[t]; bi2[t] = bi1[t]; bs1[t] = v; bi1[t] = code; }
                        else if (v < bs2[t]) { bs2[t] = v; bi2[t] = code; }
                    }
                }
            }
            MBARRIER_ARRIVE(sb + BAR_BE(s));
        }

        // quad-lane merge (lanes sharing l>>2 own the same 4 token rows)
        unsigned long long k1[4], k2[4];
#pragma unroll
        for (int t = 0; t < 4; t++) { k1[t] = packkey(bs1[t], bi1[t]); k2[t] = packkey(bs2[t], bi2[t]); }
#pragma unroll
        for (int off = 1; off <= 2; off <<= 1) {
#pragma unroll
            for (int t = 0; t < 4; t++) {
                unsigned long long o1 = __shfl_xor_sync(0xffffffffu, k1[t], off);
                unsigned long long o2 = __shfl_xor_sync(0xffffffffu, k2[t], off);
                unsigned long long n1 = u64min(k1[t], o1);
                unsigned long long n2 = u64min(u64max(k1[t], o1), u64min(k2[t], o2));
                k1[t] = n1; k2[t] = n2;
            }
        }
        uint4* mrg = (uint4*)(smem + SMRG);
        if ((l & 3) == 0) {
#pragma unroll
            for (int t = 0; t < 4; t++) {
                int tok = m0 + (t >> 1) * 16 + (l >> 2) + 8 * (t & 1);
                mrg[tok * 4 + (wid >> 2)] = make_uint4(
                    (uint32_t)(k1[t] >> 32), (uint32_t)k1[t],
                    (uint32_t)(k2[t] >> 32), (uint32_t)k2[t]);
            }
        }
        asm volatile("bar.sync 1, 512;" ::: "memory");
        if (tid < 128) {
            unsigned long long m1 = 0xFFFFFFFFFFFFFFFFULL, m2 = 0xFFFFFFFFFFFFFFFFULL;
#pragma unroll
            for (int g = 0; g < 4; g++) {
                uint4 e = mrg[tid * 4 + g];
                unsigned long long c1 = ((unsigned long long)e.x << 32) | e.y;
                unsigned long long c2 = ((unsigned long long)e.z << 32) | e.w;
                unsigned long long n1 = u64min(m1, c1);
                unsigned long long n2 = u64min(u64max(m1, c1), u64min(m2, c2));
                m1 = n1; m2 = n2;
            }
            float gap = unpackscore(m2) - unpackscore(m1);
            g_cand[blockIdx.x * MTILE + tid] = make_int4(
                (int)(uint32_t)m1, (int)(uint32_t)m2, __float_as_int(gap), 0);
        }
    } else if (tid == 512) {
        // producer
        const char* asrc = (const char*)g_ximg4 + (size_t)blockIdx.x * 65536;
        const char* bsrc = (const char*)g_cbimg4;
        MBARRIER_EXPECT_TX(sb + BAR_AF, 65536);
        bulk_g2s(sb + SA, asrc, 32768, sb + BAR_AF);
        bulk_g2s(sb + SA + 32768, asrc + 32768, 32768, sb + BAR_AF);
        for (int i = 0; i < NCHUNK; i++) {
            int s = i & 1;
            MBARRIER_WAIT_PARITY(sb + BAR_BE(s), ((i >> 1) & 1) ^ 1);
            MBARRIER_EXPECT_TX(sb + BAR_BF(s), 65536 + 512);
            bulk_g2s(sb + SB + s * 65536, bsrc + (size_t)i * 65536, 65536, sb + BAR_BF(s));
            bulk_g2s(sb + SE2 + s * 512, (const char*)g_e2h + (size_t)i * 512, 512, sb + BAR_BF(s));
        }
    }
}

// ---------------------------------------------------------------------------
// Fixup: exact fp32 recheck of top-2 where the approx gap is small. Warp/token.
// ---------------------------------------------------------------------------
__global__ void fixup_kernel(const float* __restrict__ x, const float* __restrict__ cb) {
    int w = (blockIdx.x * blockDim.x + threadIdx.x) >> 5;
    int l = threadIdx.x & 31;
    if (w >= NTOK) return;
    int4 cd = g_cand[w];
    float gap = __int_as_float(cd.z);
    if (gap > 0.15f) { if (l == 0) g_idx[w] = cd.x; return; }
    int b = w >> 10, hw = w & (HW_ - 1);
    const float* xp = x + (size_t)b * C_ * HW_ + hw;
    const float* c1 = cb + (size_t)cd.x * C_;
    const float* c2 = cb + (size_t)cd.y * C_;
    float d1 = 0.0f, d2 = 0.0f;
    for (int c = l; c < C_; c += 32) {
        float xv = xp[(size_t)c * HW_];
        d1 += xv * c1[c];
        d2 += xv * c2[c];
    }
#pragma unroll
    for (int o = 16; o; o >>= 1) {
        d1 += __shfl_xor_sync(0xffffffffu, d1, o);
        d2 += __shfl_xor_sync(0xffffffffu, d2, o);
    }
    if (l == 0) {
        float e1 = g_e2h[cd.x] - d1, e2v = g_e2h[cd.y] - d2;
        int pick = cd.x;
        if (e2v < e1 || (e2v == e1 && cd.y < cd.x)) pick = cd.y;
        g_idx[w] = pick;
    }
}

// ---------------------------------------------------------------------------
// Gather quantized output [B,C,H,W] + MSE partial sums.
// ---------------------------------------------------------------------------
__global__ __launch_bounds__(256)
void gather_loss_kernel(const float* __restrict__ x,
                        const float* __restrict__ cb,
                        float* __restrict__ out) {
    __shared__ float warp_sums[8];
    int o = blockIdx.x * blockDim.x + threadIdx.x;
    int hw = o & (HW_ - 1);
    int bc = o >> 10;
    int c  = bc & (C_ - 1);
    int b  = bc >> 8;
    int n  = b * HW_ + hw;

    int idx  = g_idx[n];
    float q  = __ldg(&cb[(size_t)idx * C_ + c]);
    float xv = x[o];
    out[o] = q;
    float d = q - xv;
    float s = d * d;
#pragma unroll
    for (int off = 16; off; off >>= 1) s += __shfl_xor_sync(0xffffffffu, s, off);
    int lane = threadIdx.x & 31, wid = threadIdx.x >> 5;
    if (lane == 0) warp_sums[wid] = s;
    __syncthreads();
    if (wid == 0) {
        float v = (lane < 8) ? warp_sums[lane] : 0.0f;
#pragma unroll
        for (int off = 4; off; off >>= 1) v += __shfl_xor_sync(0xffffffffu, v, off);
        if (lane == 0) atomicAdd(&g_loss, v);
    }
}

__global__ void finalize_kernel(float* __restrict__ out, int out_size) {
    float m = g_loss * (1.0f / (float)NOUT);
    if (out_size >= NOUT + 1) out[NOUT] = m;
    if (out_size >= NOUT + 2) out[NOUT + 1] = m;
}

// ---------------------------------------------------------------------------
extern "C" void kernel_launch(void* const* d_in, const int* in_sizes, int n_in,
                              void* d_out, int out_size) {
    const float* x  = (const float*)d_in[0];   // [16,256,32,32]
    const float* cb = (const float*)d_in[1];   // [8192,256]
    float* out = (float*)d_out;

    cudaFuncSetAttribute(vq_main_kernel, cudaFuncAttributeMaxDynamicSharedMemorySize, SMEM_SZ);

    prep_cb_kernel<<<K_ / 8, 256>>>(cb);
    dim3 gx(32, 8, 16), bx(32, 8);
    prep_x_kernel<<<gx, bx>>>(x);
    noop_kernel<<<1, 1>>>();                               // pad: vq_main -> launch #4
    vq_main_kernel<<<NCTA, 544, SMEM_SZ>>>();
    fixup_kernel<<<NTOK / 8, 256>>>(x, cb);
    gather_loss_kernel<<<NOUT / 256, 256>>>(x, cb, out);
    finalize_kernel<<<1, 1>>>(out, out_size);
}